// round 16
// baseline (speedup 1.0000x reference)
#include <cuda_runtime.h>
#include <cuda_fp16.h>
#include <cstdint>

#define N_NODES 50000
#define N_EDGES 1600000
#define SCAN_NB ((N_NODES + 255) / 256)   // 196
#define NBINS 512

// Scratch (device globals: allocation-free, graph-capturable; zero at load)
__device__ __half g_Ah[N_NODES * 64];               // dinv-scaled xW in fp16
__device__ float  g_B[N_NODES * 64];                // H buffer (fp32, node-sequential)
__device__ float  g_dinv[N_NODES];
__device__ unsigned long long g_pack[N_NODES];      // (cnt<<32)|fix(sum ew); self-clearing
__device__ unsigned long long g_state[SCAN_NB];     // lookback state; cleared by scatter
__device__ int   g_rowptr[N_NODES + 1];
__device__ int   g_rank[N_EDGES];                   // per-edge rank within dst bucket
__device__ int2  g_meta[N_EDGES];                   // (src, ew) sorted by dst
__device__ int   g_hist[NBINS];                     // degree histogram (self-clearing)
__device__ int   g_binbase[NBINS];
__device__ int   g_btmp[N_NODES];                   // (bin<<20)|rank-in-bin
__device__ int   g_perm[N_NODES];                   // nodes in descending-degree order

// ---------------- prelude ----------------

__global__ void k_count(const float* __restrict__ ew, const int* __restrict__ dst,
                        unsigned long long* __restrict__ pack, int* __restrict__ rank,
                        int E) {
    int i = blockIdx.x * blockDim.x + threadIdx.x;
    cudaGridDependencySynchronize();
    if (i < E) {
        unsigned q = __float2uint_rn(ew[i] * 1048576.0f);
        unsigned long long old =
            atomicAdd(&pack[dst[i]], (1ull << 32) | (unsigned long long)q);
        rank[i] = (int)(old >> 32);
    }
}

// Exclusive scan (decoupled lookback) + dinv + FUSED degree histogram/btmp.
__global__ void k_scan(unsigned long long* __restrict__ pack,
                       int* __restrict__ rowptr, float* __restrict__ dinv,
                       unsigned long long* __restrict__ state,
                       int* __restrict__ hist, int* __restrict__ btmp,
                       int n, int E) {
    __shared__ int sh[256];
    __shared__ int s_prefix;
    const int b = blockIdx.x;
    const int i = b * 256 + threadIdx.x;

    cudaGridDependencySynchronize();

    unsigned long long p = (i < n) ? pack[i] : 0ull;
    int v = (int)(p >> 32);
    if (i < n) {
        pack[i] = 0ull;   // self-clear for next graph replay
        float deg = 1.0f + (float)(unsigned)(p & 0xFFFFFFFFull) * (1.0f / 1048576.0f);
        dinv[i] = rsqrtf(deg);
        // fused histogram (was k_hist): degree v is live here
        int c = min(v, NBINS - 1);
        int r = atomicAdd(&hist[c], 1);
        btmp[i] = (c << 20) | r;
    }

    sh[threadIdx.x] = v;
    __syncthreads();
#pragma unroll
    for (int off = 1; off < 256; off <<= 1) {
        int t = (threadIdx.x >= off) ? sh[threadIdx.x - off] : 0;
        __syncthreads();
        sh[threadIdx.x] += t;
        __syncthreads();
    }
    const int incl = sh[threadIdx.x];
    const int total = sh[255];

    if (threadIdx.x < 32) {
        const int lane = threadIdx.x;
        if (lane == 0) {
            unsigned long long st0 =
                ((unsigned long long)total << 2) | (b == 0 ? 2ull : 1ull);
            atomicExch(&state[b], st0);
        }
        int prefix = 0;
        if (b > 0) {
            int j = b - 1;
            while (true) {
                int idx = j - lane;
                unsigned long long s =
                    (idx >= 0) ? atomicAdd(&state[idx], 0ull) : 2ull;
                unsigned st = (unsigned)(s & 3ull);
                unsigned ready = __ballot_sync(0xffffffffu, st != 0u);
                if (ready != 0xffffffffu) continue;
                unsigned inclmask = __ballot_sync(0xffffffffu, st == 2u);
                if (inclmask) {
                    int l2 = __ffs(inclmask) - 1;
                    int contrib = (lane <= l2) ? (int)(s >> 2) : 0;
#pragma unroll
                    for (int o = 16; o; o >>= 1)
                        contrib += __shfl_down_sync(0xffffffffu, contrib, o);
                    prefix += __shfl_sync(0xffffffffu, contrib, 0);
                    break;
                } else {
                    int contrib = (idx >= 0) ? (int)(s >> 2) : 0;
#pragma unroll
                    for (int o = 16; o; o >>= 1)
                        contrib += __shfl_down_sync(0xffffffffu, contrib, o);
                    prefix += __shfl_sync(0xffffffffu, contrib, 0);
                    j -= 32;
                }
            }
            if (lane == 0)
                atomicExch(&state[b],
                           ((unsigned long long)(prefix + total) << 2) | 2ull);
        }
        if (lane == 0) s_prefix = prefix;
    }
    __syncthreads();

    if (i < n) {
        rowptr[i] = s_prefix + incl - v;
        if (i == n - 1) rowptr[n] = E;
    }
}

// Scatter: meta = (src, raw ew). No random gathers (dinv folded into Ah rows).
__global__ void k_scatter(const int* __restrict__ src, const int* __restrict__ dst,
                          const float* __restrict__ ew,
                          const int* __restrict__ rowptr, const int* __restrict__ rank,
                          int2* __restrict__ meta, unsigned long long* __restrict__ state,
                          int E) {
    int i = blockIdx.x * blockDim.x + threadIdx.x;
    int s = 0, d = 0;
    float w0 = 0.0f;
    if (i < E) { s = src[i]; d = dst[i]; w0 = ew[i]; }
    cudaGridDependencySynchronize();
    if (i < SCAN_NB) state[i] = 0ull;
    if (i < E) {
        int p = rowptr[d] + rank[i];
        meta[p] = make_int2(s, __float_as_int(w0));
    }
}

// ---------------- degree-sorted permutation tail (side stream) ----------

__global__ void k_binscan(const int* __restrict__ hist, int* __restrict__ binbase) {
    __shared__ int sh[NBINS];
    int t = threadIdx.x;
    int v = hist[NBINS - 1 - t];
    sh[t] = v;
    __syncthreads();
#pragma unroll
    for (int off = 1; off < NBINS; off <<= 1) {
        int u = (t >= off) ? sh[t - off] : 0;
        __syncthreads();
        sh[t] += u;
        __syncthreads();
    }
    binbase[NBINS - 1 - t] = sh[t] - v;  // exclusive, heavy bins first
}

__global__ void k_perm(const int* __restrict__ btmp, const int* __restrict__ binbase,
                       int* __restrict__ perm, int* __restrict__ hist, int n) {
    int i = blockIdx.x * blockDim.x + threadIdx.x;
    if (i < NBINS) hist[i] = 0;          // self-clear for next replay
    if (i < n) {
        int b = btmp[i];
        int c = b >> 20;
        int r = b & 0xFFFFF;
        perm[binbase[c] + r] = i;
    }
}

// ---------------- GEMM: Ah = dinv-scaled xW in fp16, 4 rows/warp -----------

template <int FIN, int FOUT, bool RELU_IN>
__global__ void gemm_xw(const float* __restrict__ X, const float* __restrict__ W,
                        const float* __restrict__ dinv, __half* __restrict__ xWh, int n) {
    __shared__ float Ws[FIN * FOUT];
    for (int i = threadIdx.x; i < FIN * FOUT; i += blockDim.x) Ws[i] = W[i];
    __syncthreads();

    cudaGridDependencySynchronize();

    const int lane = threadIdx.x & 31;
    const int wq = blockIdx.x * (blockDim.x >> 5) + (threadIdx.x >> 5);
    const int row0 = wq * 4;
    if (row0 >= n) return;

    constexpr int XPL = FIN / 32;
    const int c0 = lane * 2;
    const bool act = (c0 < FOUT);

    float xr[4][XPL];
#pragma unroll
    for (int r = 0; r < 4; r++) {
        int row = row0 + r;
        if (row < n) {
            if (XPL == 4) {
                float4 t = reinterpret_cast<const float4*>(X)[row * (FIN / 4) + lane];
                xr[r][0] = t.x; xr[r][1] = t.y; xr[r][2] = t.z; xr[r][3] = t.w;
            } else {
                float2 t = reinterpret_cast<const float2*>(X)[row * (FIN / 2) + lane];
                xr[r][0] = t.x; xr[r][1] = t.y;
            }
            if (RELU_IN) {
#pragma unroll
                for (int j = 0; j < XPL; j++) xr[r][j] = fmaxf(xr[r][j], 0.0f);
            }
        } else {
#pragma unroll
            for (int j = 0; j < XPL; j++) xr[r][j] = 0.0f;
        }
    }

    unsigned long long acc[4] = {0ull, 0ull, 0ull, 0ull};

#pragma unroll
    for (int k = 0; k < FIN; k++) {
        unsigned long long ww = 0ull;
        if (act)
            ww = *reinterpret_cast<const unsigned long long*>(&Ws[k * FOUT + c0]);
#pragma unroll
        for (int r = 0; r < 4; r++) {
            float xk = __shfl_sync(0xffffffffu, xr[r][k % XPL], k / XPL);
            if (act) {
                unsigned long long xx;
                asm("mov.b64 %0, {%1, %1};" : "=l"(xx) : "f"(xk));
                asm("fma.rn.f32x2 %0, %1, %2, %3;"
                    : "=l"(acc[r]) : "l"(xx), "l"(ww), "l"(acc[r]));
            }
        }
    }

    if (act) {
#pragma unroll
        for (int r = 0; r < 4; r++) {
            int row = row0 + r;
            if (row < n) {
                float di = __ldg(&dinv[row]);
                float2 a;
                asm("mov.b64 {%0, %1}, %2;" : "=f"(a.x), "=f"(a.y) : "l"(acc[r]));
                __half2 h = __floats2half2_rn(a.x * di, a.y * di);
                *reinterpret_cast<__half2*>(xWh + (size_t)row * FOUT + c0) = h;
            }
        }
    }
}

// ---------------- CSR aggregation (dinv pre-folded into Ah rows) -----------

template <int FOUT>
__global__ void agg_csr(const __half* __restrict__ xWh, const int* __restrict__ rowptr,
                        const int2* __restrict__ meta, const float* __restrict__ bias,
                        const float* __restrict__ dinv, const int* __restrict__ perm,
                        float* __restrict__ H, int n) {
    const int warp = (blockIdx.x * blockDim.x + threadIdx.x) >> 5;
    const int lane = threadIdx.x & 31;
    const int half = lane >> 4;
    const int sub = lane & 15;
    const int idx = warp * 2 + half;
    const unsigned hmask = half ? 0xFFFF0000u : 0x0000FFFFu;
    const bool valid = idx < n;

    const int c0 = sub * 4;
    const bool act = valid && (c0 < FOUT);

    cudaGridDependencySynchronize();

    const int node = valid ? __ldg(&perm[idx]) : 0;
    float di = valid ? dinv[node] : 0.0f;

    float4 acc = make_float4(0.f, 0.f, 0.f, 0.f);
    if (act) {
        uint2 q = *reinterpret_cast<const uint2*>(xWh + (size_t)node * FOUT + c0);
        float2 f0 = __half22float2(*reinterpret_cast<__half2*>(&q.x));
        float2 f1 = __half22float2(*reinterpret_cast<__half2*>(&q.y));
        acc.x = f0.x; acc.y = f0.y; acc.z = f1.x; acc.w = f1.y;  // dinv pre-folded
    }

    int e = valid ? rowptr[node] : 0;
    const int end = valid ? rowptr[node + 1] : 0;

    int2 pr = make_int2(0, 0);
    if (e + sub < end) pr = __ldg(&meta[e + sub]);

    while (e < end) {
        const int cnt = min(end - e, 16);
        const int2 cur = pr;
        const int en = e + 16;
        if (en + sub < end) pr = __ldg(&meta[en + sub]);   // prefetch next chunk

        if (cnt == 16) {
#pragma unroll
            for (int j = 0; j < 16; j++) {
                int s = __shfl_sync(hmask, cur.x, j, 16);
                float w = __int_as_float(__shfl_sync(hmask, cur.y, j, 16));
                if (act) {
                    uint2 q = *reinterpret_cast<const uint2*>(xWh + (size_t)s * FOUT + c0);
                    float2 f0 = __half22float2(*reinterpret_cast<__half2*>(&q.x));
                    float2 f1 = __half22float2(*reinterpret_cast<__half2*>(&q.y));
                    acc.x = fmaf(w, f0.x, acc.x);
                    acc.y = fmaf(w, f0.y, acc.y);
                    acc.z = fmaf(w, f1.x, acc.z);
                    acc.w = fmaf(w, f1.y, acc.w);
                }
            }
        } else {
            for (int j = 0; j < cnt; j++) {
                int s = __shfl_sync(hmask, cur.x, j, 16);
                float w = __int_as_float(__shfl_sync(hmask, cur.y, j, 16));
                if (act) {
                    uint2 q = *reinterpret_cast<const uint2*>(xWh + (size_t)s * FOUT + c0);
                    float2 f0 = __half22float2(*reinterpret_cast<__half2*>(&q.x));
                    float2 f1 = __half22float2(*reinterpret_cast<__half2*>(&q.y));
                    acc.x = fmaf(w, f0.x, acc.x);
                    acc.y = fmaf(w, f0.y, acc.y);
                    acc.z = fmaf(w, f1.x, acc.z);
                    acc.w = fmaf(w, f1.y, acc.w);
                }
            }
        }
        e = en;
    }

    if (act) {
        float4 b = *reinterpret_cast<const float4*>(bias + c0);
        float4 o;
        o.x = fmaf(di, acc.x, b.x);
        o.y = fmaf(di, acc.y, b.y);
        o.z = fmaf(di, acc.z, b.z);
        o.w = fmaf(di, acc.w, b.w);
        *reinterpret_cast<float4*>(H + (size_t)node * FOUT + c0) = o;
    }
}

// ---------------- host launcher ----------------

template <typename... FuncArgs, typename... ActArgs>
static inline void launch_pss(dim3 g, dim3 b, cudaStream_t s,
                              void (*f)(FuncArgs...), ActArgs... args) {
    cudaLaunchConfig_t cfg = {};
    cfg.gridDim = g;
    cfg.blockDim = b;
    cfg.dynamicSmemBytes = 0;
    cfg.stream = s;
    cudaLaunchAttribute at[1];
    at[0].id = cudaLaunchAttributeProgrammaticStreamSerialization;
    at[0].val.programmaticStreamSerializationAllowed = 1;
    cfg.attrs = at;
    cfg.numAttrs = 1;
    cudaLaunchKernelEx(&cfg, f, static_cast<FuncArgs>(args)...);
}

extern "C" void kernel_launch(void* const* d_in, const int* in_sizes, int n_in,
                              void* d_out, int out_size) {
    const float* x  = (const float*)d_in[0];
    const int*   ei = (const int*)d_in[1];
    const float* ew = (const float*)d_in[2];
    const float* W1 = (const float*)d_in[3];
    const float* b1 = (const float*)d_in[4];
    const float* W2 = (const float*)d_in[5];
    const float* b2 = (const float*)d_in[6];
    const float* W3 = (const float*)d_in[7];
    const float* b3 = (const float*)d_in[8];
    float* out = (float*)d_out;

    const int n = in_sizes[0] / 128;
    const int E = in_sizes[2];
    const int* src = ei;
    const int* dst = ei + E;

    __half *Ah;
    float *B, *dinv;
    int *rowptr, *rank, *hist, *binbase, *btmp, *perm;
    int2 *meta;
    unsigned long long *pack, *state;
    cudaGetSymbolAddress((void**)&Ah, g_Ah);
    cudaGetSymbolAddress((void**)&B, g_B);
    cudaGetSymbolAddress((void**)&dinv, g_dinv);
    cudaGetSymbolAddress((void**)&pack, g_pack);
    cudaGetSymbolAddress((void**)&state, g_state);
    cudaGetSymbolAddress((void**)&rowptr, g_rowptr);
    cudaGetSymbolAddress((void**)&rank, g_rank);
    cudaGetSymbolAddress((void**)&meta, g_meta);
    cudaGetSymbolAddress((void**)&hist, g_hist);
    cudaGetSymbolAddress((void**)&binbase, g_binbase);
    cudaGetSymbolAddress((void**)&btmp, g_btmp);
    cudaGetSymbolAddress((void**)&perm, g_perm);

    const int TB = 256;
    dim3 tb(TB);
    dim3 eblk((E + TB - 1) / TB);
    dim3 nblk((n + TB - 1) / TB);
    dim3 aggblk((n + 15) / 16);   // 2 nodes/warp, 8 warps/block
    dim3 gblk((n + 31) / 32);     // 4 rows/warp, 8 warps/block
    dim3 scanblk(SCAN_NB);

    static cudaStream_t sSide = nullptr, sSide2 = nullptr;
    static cudaEvent_t evScan = nullptr, evG1 = nullptr, evPerm = nullptr;
    if (sSide == nullptr) {
        cudaStreamCreateWithFlags(&sSide, cudaStreamNonBlocking);
        cudaStreamCreateWithFlags(&sSide2, cudaStreamNonBlocking);
        cudaEventCreateWithFlags(&evScan, cudaEventDisableTiming);
        cudaEventCreateWithFlags(&evG1, cudaEventDisableTiming);
        cudaEventCreateWithFlags(&evPerm, cudaEventDisableTiming);
    }

    // ---- CSR prelude head on main stream, PDL-chained ----
    launch_pss(eblk, tb, (cudaStream_t)0, k_count, ew, dst, pack, rank, E);
    launch_pss(scanblk, tb, (cudaStream_t)0, k_scan,
               pack, rowptr, dinv, state, hist, btmp, n, E);
    cudaEventRecord(evScan, 0);

    // ---- three-way parallel after scan ----
    // side: gemm1 (needs dinv since Ah rows are dinv-scaled)
    cudaStreamWaitEvent(sSide, evScan, 0);
    gemm_xw<128, 64, false><<<gblk, TB, 0, sSide>>>(x, W1, dinv, Ah, n);
    cudaEventRecord(evG1, sSide);

    // side2: permutation tail (hist already built inside k_scan)
    cudaStreamWaitEvent(sSide2, evScan, 0);
    k_binscan<<<1, NBINS, 0, sSide2>>>(hist, binbase);
    k_perm<<<nblk, TB, 0, sSide2>>>(btmp, binbase, perm, hist, n);
    cudaEventRecord(evPerm, sSide2);

    // main: scatter (streaming only — no dinv gather)
    launch_pss(eblk, tb, (cudaStream_t)0, k_scatter,
               src, dst, ew, rowptr, rank, meta, state, E);

    // ---- join: agg1 needs scatter (stream order) + gemm1 + perm ----
    cudaStreamWaitEvent(0, evG1, 0);
    cudaStreamWaitEvent(0, evPerm, 0);
    launch_pss(aggblk, tb, (cudaStream_t)0, agg_csr<64>,
               Ah, rowptr, meta, b1, dinv, perm, B, n);

    // ---- Layer 2 ----
    launch_pss(gblk, tb, (cudaStream_t)0, gemm_xw<64, 64, true>, B, W2, dinv, Ah, n);
    launch_pss(aggblk, tb, (cudaStream_t)0, agg_csr<64>,
               Ah, rowptr, meta, b2, dinv, perm, B, n);

    // ---- Layer 3 ----
    launch_pss(gblk, tb, (cudaStream_t)0, gemm_xw<64, 40, true>, B, W3, dinv, Ah, n);
    launch_pss(aggblk, tb, (cudaStream_t)0, agg_csr<40>,
               Ah, rowptr, meta, b3, dinv, perm, out, n);
}

// round 17
// speedup vs baseline: 1.0347x; 1.0347x over previous
#include <cuda_runtime.h>
#include <cuda_fp16.h>
#include <cstdint>

#define N_NODES 50000
#define N_EDGES 1600000
#define SCAN_NB ((N_NODES + 255) / 256)   // 196
#define NBINS 512

// Scratch (device globals: allocation-free, graph-capturable; zero at load)
__device__ __half g_Ah[N_NODES * 64];               // dinv-scaled xW in fp16
__device__ float  g_B[N_NODES * 64];                // H buffer (fp32, node-sequential)
__device__ float  g_dinv[N_NODES];
__device__ unsigned long long g_pack[N_NODES];      // (cnt<<32)|fix(sum ew); self-clearing
__device__ unsigned long long g_state[SCAN_NB];     // lookback state; cleared by scatter
__device__ int   g_rowptr[N_NODES + 1];
__device__ unsigned short g_rank[N_EDGES];          // per-edge rank within dst bucket
__device__ int2  g_meta[N_EDGES];                   // (src, ew) sorted by dst
__device__ int   g_hist[NBINS];                     // degree histogram (self-clearing)
__device__ int   g_binbase[NBINS];
__device__ int   g_btmp[N_NODES];                   // (bin<<20)|rank-in-bin
__device__ int   g_perm[N_NODES];                   // nodes in descending-degree order

// ---------------- prelude ----------------

__global__ void k_count(const float* __restrict__ ew, const int* __restrict__ dst,
                        unsigned long long* __restrict__ pack,
                        unsigned short* __restrict__ rank, int E) {
    int i = blockIdx.x * blockDim.x + threadIdx.x;
    cudaGridDependencySynchronize();
    if (i < E) {
        unsigned q = __float2uint_rn(ew[i] * 1048576.0f);
        unsigned long long old =
            atomicAdd(&pack[dst[i]], (1ull << 32) | (unsigned long long)q);
        rank[i] = (unsigned short)(old >> 32);
    }
}

__global__ void k_scan(unsigned long long* __restrict__ pack,
                       int* __restrict__ rowptr, float* __restrict__ dinv,
                       unsigned long long* __restrict__ state, int n, int E) {
    __shared__ int sh[256];
    __shared__ int s_prefix;
    const int b = blockIdx.x;
    const int i = b * 256 + threadIdx.x;

    cudaGridDependencySynchronize();

    unsigned long long p = (i < n) ? pack[i] : 0ull;
    int v = (int)(p >> 32);
    if (i < n) {
        pack[i] = 0ull;   // self-clear for next graph replay
        float deg = 1.0f + (float)(unsigned)(p & 0xFFFFFFFFull) * (1.0f / 1048576.0f);
        dinv[i] = rsqrtf(deg);
    }

    sh[threadIdx.x] = v;
    __syncthreads();
#pragma unroll
    for (int off = 1; off < 256; off <<= 1) {
        int t = (threadIdx.x >= off) ? sh[threadIdx.x - off] : 0;
        __syncthreads();
        sh[threadIdx.x] += t;
        __syncthreads();
    }
    const int incl = sh[threadIdx.x];
    const int total = sh[255];

    if (threadIdx.x < 32) {
        const int lane = threadIdx.x;
        if (lane == 0) {
            unsigned long long st0 =
                ((unsigned long long)total << 2) | (b == 0 ? 2ull : 1ull);
            atomicExch(&state[b], st0);
        }
        int prefix = 0;
        if (b > 0) {
            int j = b - 1;
            while (true) {
                int idx = j - lane;
                unsigned long long s =
                    (idx >= 0) ? atomicAdd(&state[idx], 0ull) : 2ull;
                unsigned st = (unsigned)(s & 3ull);
                unsigned ready = __ballot_sync(0xffffffffu, st != 0u);
                if (ready != 0xffffffffu) continue;
                unsigned inclmask = __ballot_sync(0xffffffffu, st == 2u);
                if (inclmask) {
                    int l2 = __ffs(inclmask) - 1;
                    int contrib = (lane <= l2) ? (int)(s >> 2) : 0;
#pragma unroll
                    for (int o = 16; o; o >>= 1)
                        contrib += __shfl_down_sync(0xffffffffu, contrib, o);
                    prefix += __shfl_sync(0xffffffffu, contrib, 0);
                    break;
                } else {
                    int contrib = (idx >= 0) ? (int)(s >> 2) : 0;
#pragma unroll
                    for (int o = 16; o; o >>= 1)
                        contrib += __shfl_down_sync(0xffffffffu, contrib, o);
                    prefix += __shfl_sync(0xffffffffu, contrib, 0);
                    j -= 32;
                }
            }
            if (lane == 0)
                atomicExch(&state[b],
                           ((unsigned long long)(prefix + total) << 2) | 2ull);
        }
        if (lane == 0) s_prefix = prefix;
    }
    __syncthreads();

    if (i < n) {
        rowptr[i] = s_prefix + incl - v;
        if (i == n - 1) rowptr[n] = E;
    }
}

// Scatter: meta = (src, raw ew). No random gathers (dinv folded into Ah rows);
// rowptr gather is L1-resident (200KB fits in L1).
__global__ void k_scatter(const int* __restrict__ src, const int* __restrict__ dst,
                          const float* __restrict__ ew,
                          const int* __restrict__ rowptr,
                          const unsigned short* __restrict__ rank,
                          int2* __restrict__ meta, unsigned long long* __restrict__ state,
                          int E) {
    int i = blockIdx.x * blockDim.x + threadIdx.x;
    int s = 0, d = 0;
    float w0 = 0.0f;
    unsigned short r16 = 0;
    if (i < E) { s = src[i]; d = dst[i]; w0 = ew[i]; r16 = rank[i]; }
    cudaGridDependencySynchronize();
    if (i < SCAN_NB) state[i] = 0ull;
    if (i < E) {
        int p = rowptr[d] + (int)r16;
        meta[p] = make_int2(s, __float_as_int(w0));
    }
}

// ---------------- degree-sorted permutation (side stream) ----------

__global__ void k_hist(const int* __restrict__ rowptr, int* __restrict__ hist,
                       int* __restrict__ btmp, int n) {
    int i = blockIdx.x * blockDim.x + threadIdx.x;
    cudaGridDependencySynchronize();
    if (i < n) {
        int c = min(rowptr[i + 1] - rowptr[i], NBINS - 1);
        int r = atomicAdd(&hist[c], 1);
        btmp[i] = (c << 20) | r;
    }
}

__global__ void k_binscan(const int* __restrict__ hist, int* __restrict__ binbase) {
    __shared__ int sh[NBINS];
    cudaGridDependencySynchronize();
    int t = threadIdx.x;
    int v = hist[NBINS - 1 - t];
    sh[t] = v;
    __syncthreads();
#pragma unroll
    for (int off = 1; off < NBINS; off <<= 1) {
        int u = (t >= off) ? sh[t - off] : 0;
        __syncthreads();
        sh[t] += u;
        __syncthreads();
    }
    binbase[NBINS - 1 - t] = sh[t] - v;  // exclusive, heavy bins first
}

__global__ void k_perm(const int* __restrict__ btmp, const int* __restrict__ binbase,
                       int* __restrict__ perm, int* __restrict__ hist, int n) {
    int i = blockIdx.x * blockDim.x + threadIdx.x;
    cudaGridDependencySynchronize();
    if (i < NBINS) hist[i] = 0;          // self-clear for next replay
    if (i < n) {
        int b = btmp[i];
        int c = b >> 20;
        int r = b & 0xFFFFF;
        perm[binbase[c] + r] = i;
    }
}

// ---------------- GEMM: Ah = dinv-scaled xW in fp16, 4 rows/warp -----------

template <int FIN, int FOUT, bool RELU_IN>
__global__ void gemm_xw(const float* __restrict__ X, const float* __restrict__ W,
                        const float* __restrict__ dinv, __half* __restrict__ xWh, int n) {
    __shared__ float Ws[FIN * FOUT];
    for (int i = threadIdx.x; i < FIN * FOUT; i += blockDim.x) Ws[i] = W[i];
    __syncthreads();

    cudaGridDependencySynchronize();

    const int lane = threadIdx.x & 31;
    const int wq = blockIdx.x * (blockDim.x >> 5) + (threadIdx.x >> 5);
    const int row0 = wq * 4;
    if (row0 >= n) return;

    constexpr int XPL = FIN / 32;
    const int c0 = lane * 2;
    const bool act = (c0 < FOUT);

    float xr[4][XPL];
#pragma unroll
    for (int r = 0; r < 4; r++) {
        int row = row0 + r;
        if (row < n) {
            if (XPL == 4) {
                float4 t = reinterpret_cast<const float4*>(X)[row * (FIN / 4) + lane];
                xr[r][0] = t.x; xr[r][1] = t.y; xr[r][2] = t.z; xr[r][3] = t.w;
            } else {
                float2 t = reinterpret_cast<const float2*>(X)[row * (FIN / 2) + lane];
                xr[r][0] = t.x; xr[r][1] = t.y;
            }
            if (RELU_IN) {
#pragma unroll
                for (int j = 0; j < XPL; j++) xr[r][j] = fmaxf(xr[r][j], 0.0f);
            }
        } else {
#pragma unroll
            for (int j = 0; j < XPL; j++) xr[r][j] = 0.0f;
        }
    }

    unsigned long long acc[4] = {0ull, 0ull, 0ull, 0ull};

#pragma unroll
    for (int k = 0; k < FIN; k++) {
        unsigned long long ww = 0ull;
        if (act)
            ww = *reinterpret_cast<const unsigned long long*>(&Ws[k * FOUT + c0]);
#pragma unroll
        for (int r = 0; r < 4; r++) {
            float xk = __shfl_sync(0xffffffffu, xr[r][k % XPL], k / XPL);
            if (act) {
                unsigned long long xx;
                asm("mov.b64 %0, {%1, %1};" : "=l"(xx) : "f"(xk));
                asm("fma.rn.f32x2 %0, %1, %2, %3;"
                    : "=l"(acc[r]) : "l"(xx), "l"(ww), "l"(acc[r]));
            }
        }
    }

    if (act) {
#pragma unroll
        for (int r = 0; r < 4; r++) {
            int row = row0 + r;
            if (row < n) {
                float di = __ldg(&dinv[row]);
                float2 a;
                asm("mov.b64 {%0, %1}, %2;" : "=f"(a.x), "=f"(a.y) : "l"(acc[r]));
                __half2 h = __floats2half2_rn(a.x * di, a.y * di);
                *reinterpret_cast<__half2*>(xWh + (size_t)row * FOUT + c0) = h;
            }
        }
    }
}

// ---------------- CSR aggregation (dinv pre-folded into Ah rows) -----------

template <int FOUT>
__global__ void agg_csr(const __half* __restrict__ xWh, const int* __restrict__ rowptr,
                        const int2* __restrict__ meta, const float* __restrict__ bias,
                        const float* __restrict__ dinv, const int* __restrict__ perm,
                        float* __restrict__ H, int n) {
    const int warp = (blockIdx.x * blockDim.x + threadIdx.x) >> 5;
    const int lane = threadIdx.x & 31;
    const int half = lane >> 4;
    const int sub = lane & 15;
    const int idx = warp * 2 + half;
    const unsigned hmask = half ? 0xFFFF0000u : 0x0000FFFFu;
    const bool valid = idx < n;

    const int c0 = sub * 4;
    const bool act = valid && (c0 < FOUT);

    cudaGridDependencySynchronize();

    const int node = valid ? __ldg(&perm[idx]) : 0;
    float di = valid ? dinv[node] : 0.0f;

    float4 acc = make_float4(0.f, 0.f, 0.f, 0.f);
    if (act) {
        uint2 q = *reinterpret_cast<const uint2*>(xWh + (size_t)node * FOUT + c0);
        float2 f0 = __half22float2(*reinterpret_cast<__half2*>(&q.x));
        float2 f1 = __half22float2(*reinterpret_cast<__half2*>(&q.y));
        acc.x = f0.x; acc.y = f0.y; acc.z = f1.x; acc.w = f1.y;  // dinv pre-folded
    }

    int e = valid ? rowptr[node] : 0;
    const int end = valid ? rowptr[node + 1] : 0;

    int2 pr = make_int2(0, 0);
    if (e + sub < end) pr = __ldg(&meta[e + sub]);

    while (e < end) {
        const int cnt = min(end - e, 16);
        const int2 cur = pr;
        const int en = e + 16;
        if (en + sub < end) pr = __ldg(&meta[en + sub]);   // prefetch next chunk

        if (cnt == 16) {
#pragma unroll
            for (int j = 0; j < 16; j++) {
                int s = __shfl_sync(hmask, cur.x, j, 16);
                float w = __int_as_float(__shfl_sync(hmask, cur.y, j, 16));
                if (act) {
                    uint2 q = *reinterpret_cast<const uint2*>(xWh + (size_t)s * FOUT + c0);
                    float2 f0 = __half22float2(*reinterpret_cast<__half2*>(&q.x));
                    float2 f1 = __half22float2(*reinterpret_cast<__half2*>(&q.y));
                    acc.x = fmaf(w, f0.x, acc.x);
                    acc.y = fmaf(w, f0.y, acc.y);
                    acc.z = fmaf(w, f1.x, acc.z);
                    acc.w = fmaf(w, f1.y, acc.w);
                }
            }
        } else {
            for (int j = 0; j < cnt; j++) {
                int s = __shfl_sync(hmask, cur.x, j, 16);
                float w = __int_as_float(__shfl_sync(hmask, cur.y, j, 16));
                if (act) {
                    uint2 q = *reinterpret_cast<const uint2*>(xWh + (size_t)s * FOUT + c0);
                    float2 f0 = __half22float2(*reinterpret_cast<__half2*>(&q.x));
                    float2 f1 = __half22float2(*reinterpret_cast<__half2*>(&q.y));
                    acc.x = fmaf(w, f0.x, acc.x);
                    acc.y = fmaf(w, f0.y, acc.y);
                    acc.z = fmaf(w, f1.x, acc.z);
                    acc.w = fmaf(w, f1.y, acc.w);
                }
            }
        }
        e = en;
    }

    if (act) {
        float4 b = *reinterpret_cast<const float4*>(bias + c0);
        float4 o;
        o.x = fmaf(di, acc.x, b.x);
        o.y = fmaf(di, acc.y, b.y);
        o.z = fmaf(di, acc.z, b.z);
        o.w = fmaf(di, acc.w, b.w);
        *reinterpret_cast<float4*>(H + (size_t)node * FOUT + c0) = o;
    }
}

// ---------------- host launcher ----------------

template <typename... FuncArgs, typename... ActArgs>
static inline void launch_pss(dim3 g, dim3 b, cudaStream_t s,
                              void (*f)(FuncArgs...), ActArgs... args) {
    cudaLaunchConfig_t cfg = {};
    cfg.gridDim = g;
    cfg.blockDim = b;
    cfg.dynamicSmemBytes = 0;
    cfg.stream = s;
    cudaLaunchAttribute at[1];
    at[0].id = cudaLaunchAttributeProgrammaticStreamSerialization;
    at[0].val.programmaticStreamSerializationAllowed = 1;
    cfg.attrs = at;
    cfg.numAttrs = 1;
    cudaLaunchKernelEx(&cfg, f, static_cast<FuncArgs>(args)...);
}

extern "C" void kernel_launch(void* const* d_in, const int* in_sizes, int n_in,
                              void* d_out, int out_size) {
    const float* x  = (const float*)d_in[0];
    const int*   ei = (const int*)d_in[1];
    const float* ew = (const float*)d_in[2];
    const float* W1 = (const float*)d_in[3];
    const float* b1 = (const float*)d_in[4];
    const float* W2 = (const float*)d_in[5];
    const float* b2 = (const float*)d_in[6];
    const float* W3 = (const float*)d_in[7];
    const float* b3 = (const float*)d_in[8];
    float* out = (float*)d_out;

    const int n = in_sizes[0] / 128;
    const int E = in_sizes[2];
    const int* src = ei;
    const int* dst = ei + E;

    __half *Ah;
    float *B, *dinv;
    int *rowptr, *hist, *binbase, *btmp, *perm;
    unsigned short *rank;
    int2 *meta;
    unsigned long long *pack, *state;
    cudaGetSymbolAddress((void**)&Ah, g_Ah);
    cudaGetSymbolAddress((void**)&B, g_B);
    cudaGetSymbolAddress((void**)&dinv, g_dinv);
    cudaGetSymbolAddress((void**)&pack, g_pack);
    cudaGetSymbolAddress((void**)&state, g_state);
    cudaGetSymbolAddress((void**)&rowptr, g_rowptr);
    cudaGetSymbolAddress((void**)&rank, g_rank);
    cudaGetSymbolAddress((void**)&meta, g_meta);
    cudaGetSymbolAddress((void**)&hist, g_hist);
    cudaGetSymbolAddress((void**)&binbase, g_binbase);
    cudaGetSymbolAddress((void**)&btmp, g_btmp);
    cudaGetSymbolAddress((void**)&perm, g_perm);

    const int TB = 256;
    dim3 tb(TB);
    dim3 eblk((E + TB - 1) / TB);
    dim3 nblk((n + TB - 1) / TB);
    dim3 aggblk((n + 15) / 16);   // 2 nodes/warp, 8 warps/block
    dim3 gblk((n + 31) / 32);     // 4 rows/warp, 8 warps/block
    dim3 scanblk(SCAN_NB);

    static cudaStream_t sSide = nullptr, sSide2 = nullptr;
    static cudaEvent_t evScan = nullptr, evG1 = nullptr, evPerm = nullptr;
    if (sSide == nullptr) {
        cudaStreamCreateWithFlags(&sSide, cudaStreamNonBlocking);
        cudaStreamCreateWithFlags(&sSide2, cudaStreamNonBlocking);
        cudaEventCreateWithFlags(&evScan, cudaEventDisableTiming);
        cudaEventCreateWithFlags(&evG1, cudaEventDisableTiming);
        cudaEventCreateWithFlags(&evPerm, cudaEventDisableTiming);
    }

    // ---- CSR prelude head on main stream, PDL-chained ----
    launch_pss(eblk, tb, (cudaStream_t)0, k_count, ew, dst, pack, rank, E);
    launch_pss(scanblk, tb, (cudaStream_t)0, k_scan, pack, rowptr, dinv, state, n, E);
    cudaEventRecord(evScan, 0);

    // ---- three-way parallel after scan ----
    // side: gemm1 (needs dinv since Ah rows are dinv-scaled)
    cudaStreamWaitEvent(sSide, evScan, 0);
    launch_pss(gblk, tb, sSide, gemm_xw<128, 64, false>, x, W1, dinv, Ah, n);
    cudaEventRecord(evG1, sSide);

    // side2: degree-sorted permutation (PDL-chained within the stream)
    cudaStreamWaitEvent(sSide2, evScan, 0);
    launch_pss(nblk, tb, sSide2, k_hist, rowptr, hist, btmp, n);
    launch_pss(dim3(1), dim3(NBINS), sSide2, k_binscan, hist, binbase);
    launch_pss(nblk, tb, sSide2, k_perm, btmp, binbase, perm, hist, n);
    cudaEventRecord(evPerm, sSide2);

    // main: scatter (streaming only — no random dinv gather)
    launch_pss(eblk, tb, (cudaStream_t)0, k_scatter,
               src, dst, ew, rowptr, rank, meta, state, E);

    // ---- join: agg1 needs scatter (stream order) + gemm1 + perm ----
    cudaStreamWaitEvent(0, evG1, 0);
    cudaStreamWaitEvent(0, evPerm, 0);
    launch_pss(aggblk, tb, (cudaStream_t)0, agg_csr<64>,
               Ah, rowptr, meta, b1, dinv, perm, B, n);

    // ---- Layer 2 ----
    launch_pss(gblk, tb, (cudaStream_t)0, gemm_xw<64, 64, true>, B, W2, dinv, Ah, n);
    launch_pss(aggblk, tb, (cudaStream_t)0, agg_csr<64>,
               Ah, rowptr, meta, b2, dinv, perm, B, n);

    // ---- Layer 3 ----
    launch_pss(gblk, tb, (cudaStream_t)0, gemm_xw<64, 40, true>, B, W3, dinv, Ah, n);
    launch_pss(aggblk, tb, (cudaStream_t)0, agg_csr<40>,
               Ah, rowptr, meta, b3, dinv, perm, out, n);
}